// round 2
// baseline (speedup 1.0000x reference)
#include <cuda_runtime.h>

// Problem constants
#define NROWS   65536      // 64*1024 vectors
#define DIM     64
#define KC      512
#define NQ      (NROWS*DIM)  // 4194304 quantized elements
#define THREADS 256

// Output layout (flattened tuple, f32):
//   [0]                      loss
//   [1 .. NQ]                quantized_st      (UNALIGNED base: out+1 !)
//   [1+NQ]                   perplexity
//   [2+NQ .. 2+NQ+NROWS-1]   indices (as float)

__device__ int    g_idx[NROWS];
__device__ int    g_hist[KC];
__device__ double g_sse;

__global__ void init_kernel() {
    int t = blockIdx.x * blockDim.x + threadIdx.x;
    if (t < KC) g_hist[t] = 0;
    if (t == 0) g_sse = 0.0;
}

// ---------------------------------------------------------------------------
// Argmin kernel: one thread = one input row. Embedding (512x64 f32 = 128KB)
// + per-code squared norms live in shared memory; all lanes iterate k together
// so LDS reads are broadcast (conflict-free).
//
// Numerics replicate JAX exactly where it matters:
//   d_k = fl( fl(A + b_k) - 2*c_k )    (2*c exact; fma(-2,c,t) == two-step)
// First-index tie-break via strict '<' scanning k ascending (jnp.argmin).
// ---------------------------------------------------------------------------
__global__ void __launch_bounds__(THREADS)
argmin_kernel(const float* __restrict__ inp,
              const float* __restrict__ emb,
              float* __restrict__ out_idx)
{
    extern __shared__ float smem[];
    float* sE = smem;            // KC*DIM
    float* sB = smem + KC * DIM; // KC  (squared norms)

    // Load embedding into smem (vectorized; emb base is 16B-aligned)
    for (int i = threadIdx.x; i < KC * DIM / 4; i += THREADS)
        reinterpret_cast<float4*>(sE)[i] =
            reinterpret_cast<const float4*>(emb)[i];
    __syncthreads();

    // Per-code squared norms (fp32; rounding here is far below the
    // ULP(64) grid that decides the argmin, so order is irrelevant)
    for (int k = threadIdx.x; k < KC; k += THREADS) {
        const float* e = sE + k * DIM;
        float b0 = 0.f, b1 = 0.f;
        #pragma unroll
        for (int i = 0; i < DIM; i += 2) {
            b0 = fmaf(e[i],     e[i],     b0);
            b1 = fmaf(e[i + 1], e[i + 1], b1);
        }
        sB[k] = b0 + b1;
    }
    __syncthreads();

    int row = blockIdx.x * THREADS + threadIdx.x;

    // Row of x in registers (16 x float4 = 64 floats)
    float4 x[16];
    const float4* xin = reinterpret_cast<const float4*>(inp + (size_t)row * DIM);
    #pragma unroll
    for (int i = 0; i < 16; i++) x[i] = xin[i];

    // A = sum(x*x) in fp32 (constant per row; ULP-level order differences
    // shift all d_k by whole grid steps -> argmin invariant)
    float a0 = 0.f, a1 = 0.f;
    #pragma unroll
    for (int i = 0; i < 16; i += 2) {
        a0 = fmaf(x[i].x,   x[i].x,   a0);
        a0 = fmaf(x[i].y,   x[i].y,   a0);
        a0 = fmaf(x[i].z,   x[i].z,   a0);
        a0 = fmaf(x[i].w,   x[i].w,   a0);
        a1 = fmaf(x[i+1].x, x[i+1].x, a1);
        a1 = fmaf(x[i+1].y, x[i+1].y, a1);
        a1 = fmaf(x[i+1].z, x[i+1].z, a1);
        a1 = fmaf(x[i+1].w, x[i+1].w, a1);
    }
    float A = a0 + a1;

    float best = 3.402823466e+38f;
    int   bi   = 0;

    #pragma unroll 2
    for (int k = 0; k < KC; k++) {
        const float4* e = reinterpret_cast<const float4*>(sE + k * DIM);
        float c0 = 0.f, c1 = 0.f, c2 = 0.f, c3 = 0.f;
        #pragma unroll
        for (int j = 0; j < 16; j += 4) {
            float4 e0 = e[j], e1 = e[j+1], e2 = e[j+2], e3 = e[j+3];
            c0 = fmaf(x[j].x,   e0.x, c0);
            c0 = fmaf(x[j].y,   e0.y, c0);
            c0 = fmaf(x[j].z,   e0.z, c0);
            c0 = fmaf(x[j].w,   e0.w, c0);
            c1 = fmaf(x[j+1].x, e1.x, c1);
            c1 = fmaf(x[j+1].y, e1.y, c1);
            c1 = fmaf(x[j+1].z, e1.z, c1);
            c1 = fmaf(x[j+1].w, e1.w, c1);
            c2 = fmaf(x[j+2].x, e2.x, c2);
            c2 = fmaf(x[j+2].y, e2.y, c2);
            c2 = fmaf(x[j+2].z, e2.z, c2);
            c2 = fmaf(x[j+2].w, e2.w, c2);
            c3 = fmaf(x[j+3].x, e3.x, c3);
            c3 = fmaf(x[j+3].y, e3.y, c3);
            c3 = fmaf(x[j+3].z, e3.z, c3);
            c3 = fmaf(x[j+3].w, e3.w, c3);
        }
        float c  = (c0 + c1) + (c2 + c3);
        float t  = A + sB[k];          // fl(A + b_k)
        float dd = t - 2.0f * c;       // fl(t - 2c); fma contraction is exact-equal
        if (dd < best) { best = dd; bi = k; }
    }

    g_idx[row]   = bi;
    out_idx[row] = (float)bi;
    atomicAdd(&g_hist[bi], 1);
}

// ---------------------------------------------------------------------------
// Gather + SSE: emit quantized_st = fl(x + fl(q - x)) to replicate the
// straight-through-estimator arithmetic bit-for-bit; accumulate sum((q-x)^2)
// for the loss (fp64 accumulator -> well within 1e-3 tolerance).
// NOTE: qout = out+1 is NOT 16B-aligned -> scalar stores only.
// ---------------------------------------------------------------------------
__global__ void __launch_bounds__(THREADS)
gather_kernel(const float* __restrict__ inp,
              const float* __restrict__ emb,
              float* __restrict__ qout)
{
    int g   = blockIdx.x * THREADS + threadIdx.x;  // one float4 group / thread
    int row = g >> 4;
    int col = g & 15;

    int idx = g_idx[row];
    float4 e  = reinterpret_cast<const float4*>(emb)[idx * 16 + col];  // aligned
    float4 xv = reinterpret_cast<const float4*>(inp)[g];               // aligned

    // straight-through: x + (q - x), two fp32 roundings, no fma possible
    float dx = e.x - xv.x, dy = e.y - xv.y, dz = e.z - xv.z, dw = e.w - xv.w;

    // scalar stores (destination base is out+1 -> 4B alignment only)
    float* q = qout + (size_t)g * 4;
    q[0] = xv.x + dx;
    q[1] = xv.y + dy;
    q[2] = xv.z + dz;
    q[3] = xv.w + dw;

    float s = dx * dx + dy * dy + dz * dz + dw * dw;

    // warp reduce
    #pragma unroll
    for (int off = 16; off > 0; off >>= 1)
        s += __shfl_xor_sync(0xFFFFFFFFu, s, off);

    __shared__ float ws[THREADS / 32];
    int lane = threadIdx.x & 31, wid = threadIdx.x >> 5;
    if (lane == 0) ws[wid] = s;
    __syncthreads();
    if (threadIdx.x == 0) {
        float bs = 0.f;
        #pragma unroll
        for (int w = 0; w < THREADS / 32; w++) bs += ws[w];
        atomicAdd(&g_sse, (double)bs);
    }
}

// ---------------------------------------------------------------------------
// Finalize: loss = 1.25 * mean((q-x)^2)   (e_latent == q_latent forward)
//           perplexity = exp(-sum p*log(p+1e-10)),  p = hist/N
// ---------------------------------------------------------------------------
__global__ void __launch_bounds__(512)
finalize_kernel(float* __restrict__ out)
{
    __shared__ double sh[512];
    int t = threadIdx.x;
    double p = (double)g_hist[t] * (1.0 / (double)NROWS);
    sh[t] = p * log(p + 1e-10);
    __syncthreads();
    for (int off = 256; off > 0; off >>= 1) {
        if (t < off) sh[t] += sh[t + off];
        __syncthreads();
    }
    if (t == 0) {
        out[0]      = (float)(1.25 * (g_sse * (1.0 / (double)NQ)));
        out[1 + NQ] = (float)exp(-sh[0]);
    }
}

extern "C" void kernel_launch(void* const* d_in, const int* in_sizes, int n_in,
                              void* d_out, int out_size)
{
    const float* inp = (const float*)d_in[0];
    const float* emb = (const float*)d_in[1];
    if (n_in >= 2 && in_sizes[0] == KC * DIM) {  // defensive: order swapped
        const float* t = inp; inp = emb; emb = t;
    }

    float* out   = (float*)d_out;
    float* qout  = out + 1;
    float* oidx  = out + 2 + NQ;

    const int smem_bytes = (KC * DIM + KC) * sizeof(float);  // 133120
    cudaFuncSetAttribute(argmin_kernel,
                         cudaFuncAttributeMaxDynamicSharedMemorySize,
                         smem_bytes);

    init_kernel<<<1, 512>>>();
    argmin_kernel<<<NROWS / THREADS, THREADS, smem_bytes>>>(inp, emb, oidx);
    gather_kernel<<<(NROWS * 16) / THREADS, THREADS>>>(inp, emb, qout);
    finalize_kernel<<<1, 512>>>(out);
}